// round 12
// baseline (speedup 1.0000x reference)
#include <cuda_runtime.h>

#define VOCAB_ 32000
#define B_ 1000
#define T_ 512
#define L_ 25
#define E_ 64
#define H_ 8
#define TICKS (T_ + L_ - 1)        // 536
#define SCALE 2.8853900817779268f  // 2*log2(e), folded into weights

// vproj[v][j] = SCALE*(emb[v]@W_xh0[:,j] + b_h[0][j] + sum_k W_hh[0][k][j])
__device__ float g_vproj[(size_t)VOCAB_ * H_];

typedef unsigned long long ull;

__device__ __forceinline__ void fma2(ull& d, ull a, ull b) {
    asm("fma.rn.f32x2 %0, %1, %2, %0;" : "+l"(d) : "l"(a), "l"(b));
}
__device__ __forceinline__ ull mul2(ull a, ull b) {           // d = a*b (fresh dst)
    ull d; asm("mul.rn.f32x2 %0, %1, %2;" : "=l"(d) : "l"(a), "l"(b));
    return d;
}
__device__ __forceinline__ ull pk(float lo, float hi) {
    ull r; asm("mov.b64 %0, {%1, %2};" : "=l"(r) : "f"(lo), "f"(hi)); return r;
}
__device__ __forceinline__ float2 upk(ull p) {
    float2 r; asm("mov.b64 {%0, %1}, %2;" : "=f"(r.x), "=f"(r.y) : "l"(p)); return r;
}
// y = 2*log2e*x (scale pre-folded) -> r = 1/(2^y + 1).  tanh(x) = 1 - 2r.
__device__ __forceinline__ float rstate(float y) {
    float e; asm("ex2.approx.f32 %0, %1;" : "=f"(e) : "f"(y));
    float r; asm("rcp.approx.f32 %0, %1;" : "=f"(r) : "f"(e + 1.0f));
    return r;
}

// -------- Kernel 1: vproj (x-proj + layer-0 bias + layer-0 Whh fold) --------
__global__ void vproj_kernel(const float* __restrict__ emb,
                             const float* __restrict__ W_xh0,
                             const float* __restrict__ b_h,
                             const float* __restrict__ W_hh) {
    __shared__ float sW[E_ * H_];
    __shared__ float sb[H_];    // b_h[0][j] + sum_k W_hh[0][k][j]
    for (int i = threadIdx.x; i < E_ * H_; i += blockDim.x) sW[i] = W_xh0[i];
    if (threadIdx.x < H_) {
        int j = threadIdx.x;
        float c = b_h[j];
#pragma unroll
        for (int k = 0; k < H_; k++) c += W_hh[k * H_ + j];   // layer 0 rows
        sb[j] = c;
    }
    __syncthreads();

    int v = blockIdx.x * blockDim.x + threadIdx.x;
    if (v >= VOCAB_) return;

    const float4* e4 = (const float4*)(emb + (long)v * E_);
    float acc[H_];
#pragma unroll
    for (int j = 0; j < H_; j++) acc[j] = sb[j];
#pragma unroll
    for (int k4 = 0; k4 < E_ / 4; k4++) {
        float4 ev = e4[k4];
#pragma unroll
        for (int j = 0; j < H_; j++) {
            acc[j] += ev.x * sW[(k4 * 4 + 0) * H_ + j];
            acc[j] += ev.y * sW[(k4 * 4 + 1) * H_ + j];
            acc[j] += ev.z * sW[(k4 * 4 + 2) * H_ + j];
            acc[j] += ev.w * sW[(k4 * 4 + 3) * H_ + j];
        }
    }
    float4* dst = (float4*)(g_vproj + (long)v * H_);
    dst[0] = make_float4(acc[0] * SCALE, acc[1] * SCALE, acc[2] * SCALE, acc[3] * SCALE);
    dst[1] = make_float4(acc[4] * SCALE, acc[5] * SCALE, acc[6] * SCALE, acc[7] * SCALE);
}

// ---- dual-element wavefront tick: element B's MAC block overlaps element
// A's MUFU tail (explicit intra-warp pipelining). Bias rows from smem:
// lane0's row = its x-stream (fully folded), lanes>=1 static folded bias.
template<bool GUARD>
__device__ __forceinline__ void tick2(
    ull hpA[4], ull hpB[4], const ull* wx2, const ull* whh2,
    const float* bptrA, const float* bptrB, bool valid) {

    float4 bA0 = ((const float4*)bptrA)[0];
    float4 bA1 = ((const float4*)bptrA)[1];
    float4 bB0 = ((const float4*)bptrB)[0];
    float4 bB1 = ((const float4*)bptrB)[1];

    ull vpA[4], vpB[4];
#pragma unroll
    for (int p = 0; p < 4; p++) {
        vpA[p] = __shfl_up_sync(0xffffffffu, hpA[p], 1);
        vpB[p] = __shfl_up_sync(0xffffffffu, hpB[p], 1);
    }

    ull acA[8], acB[8];
#pragma unroll
    for (int j = 0; j < 8; j++) {
        acA[j] = mul2(hpA[0], whh2[j * 4 + 0]);
        acB[j] = mul2(hpB[0], whh2[j * 4 + 0]);
        fma2(acA[j], hpA[1], whh2[j * 4 + 1]);
        fma2(acB[j], hpB[1], whh2[j * 4 + 1]);
        fma2(acA[j], hpA[2], whh2[j * 4 + 2]);
        fma2(acB[j], hpB[2], whh2[j * 4 + 2]);
        fma2(acA[j], hpA[3], whh2[j * 4 + 3]);
        fma2(acB[j], hpB[3], whh2[j * 4 + 3]);
#pragma unroll
        for (int p = 0; p < 4; p++) {
            fma2(acA[j], vpA[p], wx2[j * 4 + p]);
            fma2(acB[j], vpB[p], wx2[j * 4 + p]);
        }
    }
    const float bbA[8] = {bA0.x, bA0.y, bA0.z, bA0.w, bA1.x, bA1.y, bA1.z, bA1.w};
    const float bbB[8] = {bB0.x, bB0.y, bB0.z, bB0.w, bB1.x, bB1.y, bB1.z, bB1.w};
    float nA[8], nB[8];
#pragma unroll
    for (int j = 0; j < 8; j++) {
        float2 uA = upk(acA[j]);
        nA[j] = rstate((uA.x + uA.y) + bbA[j]);
        float2 uB = upk(acB[j]);
        nB[j] = rstate((uB.x + uB.y) + bbB[j]);
    }
    if (GUARD) {
        if (valid) {
#pragma unroll
            for (int p = 0; p < 4; p++) {
                hpA[p] = pk(nA[2 * p], nA[2 * p + 1]);
                hpB[p] = pk(nB[2 * p], nB[2 * p + 1]);
            }
        }
    } else {
#pragma unroll
        for (int p = 0; p < 4; p++) {
            hpA[p] = pk(nA[2 * p], nA[2 * p + 1]);
            hpB[p] = pk(nB[2 * p], nB[2 * p + 1]);
        }
    }
}

// -------- Kernel 2: dual-element warp wavefront, 4 warps/block --------
__global__ void __launch_bounds__(128, 1) rnn_dl_kernel(
    const int*   __restrict__ x,           // [B, T]
    const float* __restrict__ h0,          // [L, B, H]
    const float* __restrict__ W_xh_rest,   // [L-1, H, H]
    const float* __restrict__ W_hh,        // [L, H, H]
    const float* __restrict__ b_h,         // [L, H]
    const float* __restrict__ W_hy,        // [H, 1]
    const float* __restrict__ b_y,         // [1]
    float* __restrict__ out, int out_size) {

    extern __shared__ float smem[];
    float* sbias = smem;                   // [32][8] static folded biases (1 KB)
    float* sx    = smem + 32 * H_;         // [8 elems][T][8] x rows (128 KB)

    const int lane = threadIdx.x & 31;
    const int warp = threadIdx.x >> 5;     // 0..3, two elems per warp
    const int eA   = warp * 2;             // elem-in-block
    const int bA   = blockIdx.x * 8 + eA;
    const int bB   = bA + 1;
    const bool act   = (lane < L_);
    const bool hasWx = (lane >= 1) && act;
    const bool lane0 = (lane == 0);

    // ---- stage scaled x-projection rows for this block's 8 elements ----
    {
        const ulonglong2* vp = (const ulonglong2*)g_vproj;
        ulonglong2* dst = (ulonglong2*)sx;
        for (int q = threadIdx.x; q < 8 * T_; q += 128) {
            int e = q >> 9;
            int t = q & (T_ - 1);
            int id = x[(long)(blockIdx.x * 8 + e) * T_ + t];
            dst[q * 2 + 0] = vp[(long)id * 2 + 0];
            dst[q * 2 + 1] = vp[(long)id * 2 + 1];
        }
    }

    // ---- weights, r-state transformed: W' = -2*SCALE*W; bias absorbs sums ----
    ull wx2[32], whh2[32];
    float bsum[8];
#pragma unroll
    for (int j = 0; j < 8; j++) {
        float bs = 0.0f;   // SCALE * (b_j + sum_k Wx[k,j] + sum_k Whh[k,j])
#pragma unroll
        for (int p = 0; p < 4; p++) {
            float a = 0.f, c = 0.f;
            if (hasWx) {
                float w0 = W_xh_rest[((lane - 1) * H_ + 2 * p) * H_ + j];
                float w1 = W_xh_rest[((lane - 1) * H_ + 2 * p + 1) * H_ + j];
                a = -2.0f * SCALE * w0;
                c = -2.0f * SCALE * w1;
                bs += SCALE * (w0 + w1);
            }
            wx2[j * 4 + p] = pk(a, c);
            float d = 0.f, f = 0.f;
            if (act) {
                float w0 = W_hh[(lane * H_ + 2 * p) * H_ + j];
                float w1 = W_hh[(lane * H_ + 2 * p + 1) * H_ + j];
                d = -2.0f * SCALE * w0;
                f = -2.0f * SCALE * w1;
                bs += SCALE * (w0 + w1);
            }
            whh2[j * 4 + p] = pk(d, f);
        }
        if (hasWx) bs += SCALE * b_h[lane * H_ + j];
        bsum[j] = bs;
    }
    if (warp == 0) {
#pragma unroll
        for (int j = 0; j < 8; j++) sbias[lane * H_ + j] = bsum[j];
    }

    // ---- hidden state as r-form: r = (1 - h)/2 ----
    ull hpA[4], hpB[4];
#pragma unroll
    for (int p = 0; p < 4; p++) {
        float a0 = act ? h0[(lane * B_ + bA) * H_ + 2 * p]     : 0.f;
        float a1 = act ? h0[(lane * B_ + bA) * H_ + 2 * p + 1] : 0.f;
        hpA[p] = pk(0.5f * (1.0f - a0), 0.5f * (1.0f - a1));
        float c0 = act ? h0[(lane * B_ + bB) * H_ + 2 * p]     : 0.f;
        float c1 = act ? h0[(lane * B_ + bB) * H_ + 2 * p + 1] : 0.f;
        hpB[p] = pk(0.5f * (1.0f - c0), 0.5f * (1.0f - c1));
    }

    __syncthreads();

    // per-lane bias pointers: lane0 walks its x-row stream, others static bias
    const float* bptrA = lane0 ? (sx + (long)(eA + 0) * T_ * H_) : (sbias + lane * H_);
    const float* bptrB = lane0 ? (sx + (long)(eA + 1) * T_ * H_) : (sbias + lane * H_);
    const long binc = lane0 ? H_ : 0;

    int s = 0;
    // ---- ramp-up: guarded commits ----
#pragma unroll 1
    for (; s < L_ - 1; s++) {
        tick2<true>(hpA, hpB, wx2, whh2, bptrA, bptrB, s >= lane);
        bptrA += binc; bptrB += binc;
    }
    // ---- steady: unconditional commits ----
#pragma unroll 2
    for (; s < T_; s++) {
        tick2<false>(hpA, hpB, wx2, whh2, bptrA, bptrB, true);
        bptrA += binc; bptrB += binc;
    }
    bptrA -= binc; bptrB -= binc;   // clamp (lane0 invalid in ramp-down)
    // ---- ramp-down: guarded (freeze finished lanes) ----
#pragma unroll 1
    for (; s < TICKS; s++) {
        tick2<true>(hpA, hpB, wx2, whh2, bptrA, bptrB, lane >= s - (T_ - 1));
    }

    // ---- outputs: convert h = 1 - 2r ----
    if (act && out_size >= B_ + L_ * B_ * H_) {
#pragma unroll
        for (int p = 0; p < 4; p++) {
            float2 uA = upk(hpA[p]);
            out[B_ + (lane * B_ + bA) * H_ + 2 * p]     = fmaf(uA.x, -2.0f, 1.0f);
            out[B_ + (lane * B_ + bA) * H_ + 2 * p + 1] = fmaf(uA.y, -2.0f, 1.0f);
            float2 uB = upk(hpB[p]);
            out[B_ + (lane * B_ + bB) * H_ + 2 * p]     = fmaf(uB.x, -2.0f, 1.0f);
            out[B_ + (lane * B_ + bB) * H_ + 2 * p + 1] = fmaf(uB.y, -2.0f, 1.0f);
        }
    }
    if (lane == L_ - 1) {
        float sA = b_y[0], sB = b_y[0];
#pragma unroll
        for (int p = 0; p < 4; p++) {
            float2 uA = upk(hpA[p]);
            float2 uB = upk(hpB[p]);
            float w0 = W_hy[2 * p], w1 = W_hy[2 * p + 1];
            sA += fmaf(uA.x, -2.0f, 1.0f) * w0 + fmaf(uA.y, -2.0f, 1.0f) * w1;
            sB += fmaf(uB.x, -2.0f, 1.0f) * w0 + fmaf(uB.y, -2.0f, 1.0f) * w1;
        }
        if (bA < out_size) out[bA] = sA;
        if (bB < out_size) out[bB] = sB;
    }
}

extern "C" void kernel_launch(void* const* d_in, const int* in_sizes, int n_in,
                              void* d_out, int out_size) {
    const int*   x          = (const int*)d_in[0];
    const float* h0         = (const float*)d_in[1];
    const float* emb        = (const float*)d_in[2];
    const float* W_xh0      = (const float*)d_in[3];
    const float* W_xh_rest  = (const float*)d_in[4];
    const float* W_hh       = (const float*)d_in[5];
    const float* b_h        = (const float*)d_in[6];
    const float* W_hy       = (const float*)d_in[7];
    const float* b_y        = (const float*)d_in[8];

    vproj_kernel<<<(VOCAB_ + 255) / 256, 256>>>(emb, W_xh0, b_h, W_hh);

    const int smem_bytes = (32 * H_ + 8 * T_ * H_) * 4;   // 1 KB + 128 KB
    cudaFuncSetAttribute(rnn_dl_kernel,
                         cudaFuncAttributeMaxDynamicSharedMemorySize, smem_bytes);
    rnn_dl_kernel<<<B_ / 8, 128, smem_bytes>>>(x, h0, W_xh_rest, W_hh, b_h,
                                               W_hy, b_y, (float*)d_out, out_size);
}

// round 13
// speedup vs baseline: 1.0052x; 1.0052x over previous
#include <cuda_runtime.h>

#define VOCAB_ 32000
#define B_ 1000
#define T_ 512
#define L_ 25
#define E_ 64
#define H_ 8
#define TICKS (T_ + L_ - 1)        // 536
#define SCALE 2.8853900817779268f  // 2*log2(e), folded into weights

// vproj[v][j] = 2^( SCALE*(emb[v]@W_xh0[:,j] + b_h[0][j] + sum_k W_hh[0][k][j]) )
// (exponential of the full folded layer-0 constant -> multiplies into ex2 output)
__device__ float g_vproj[(size_t)VOCAB_ * H_];

typedef unsigned long long ull;

__device__ __forceinline__ void fma2(ull& d, ull a, ull b) {
    asm("fma.rn.f32x2 %0, %1, %2, %0;" : "+l"(d) : "l"(a), "l"(b));
}
__device__ __forceinline__ ull mul2(ull a, ull b) {           // d = a*b (fresh dst)
    ull d; asm("mul.rn.f32x2 %0, %1, %2;" : "=l"(d) : "l"(a), "l"(b));
    return d;
}
__device__ __forceinline__ ull pk(float lo, float hi) {
    ull r; asm("mov.b64 %0, {%1, %2};" : "=l"(r) : "f"(lo), "f"(hi)); return r;
}
__device__ __forceinline__ float2 upk(ull p) {
    float2 r; asm("mov.b64 {%0, %1}, %2;" : "=f"(r.x), "=f"(r.y) : "l"(p)); return r;
}
__device__ __forceinline__ float ex2f(float y) {
    float e; asm("ex2.approx.f32 %0, %1;" : "=f"(e) : "f"(y)); return e;
}
__device__ __forceinline__ float rcpf(float d) {
    float r; asm("rcp.approx.f32 %0, %1;" : "=f"(r) : "f"(d)); return r;
}

// -------- Kernel 1: vproj = 2^(scaled xproj + layer-0 bias + Whh fold) --------
__global__ void vproj_kernel(const float* __restrict__ emb,
                             const float* __restrict__ W_xh0,
                             const float* __restrict__ b_h,
                             const float* __restrict__ W_hh) {
    __shared__ float sW[E_ * H_];
    __shared__ float sb[H_];    // b_h[0][j] + sum_k W_hh[0][k][j]
    for (int i = threadIdx.x; i < E_ * H_; i += blockDim.x) sW[i] = W_xh0[i];
    if (threadIdx.x < H_) {
        int j = threadIdx.x;
        float c = b_h[j];
#pragma unroll
        for (int k = 0; k < H_; k++) c += W_hh[k * H_ + j];   // layer 0 rows
        sb[j] = c;
    }
    __syncthreads();

    int v = blockIdx.x * blockDim.x + threadIdx.x;
    if (v >= VOCAB_) return;

    const float4* e4 = (const float4*)(emb + (long)v * E_);
    float acc[H_];
#pragma unroll
    for (int j = 0; j < H_; j++) acc[j] = sb[j];
#pragma unroll
    for (int k4 = 0; k4 < E_ / 4; k4++) {
        float4 ev = e4[k4];
#pragma unroll
        for (int j = 0; j < H_; j++) {
            acc[j] += ev.x * sW[(k4 * 4 + 0) * H_ + j];
            acc[j] += ev.y * sW[(k4 * 4 + 1) * H_ + j];
            acc[j] += ev.z * sW[(k4 * 4 + 2) * H_ + j];
            acc[j] += ev.w * sW[(k4 * 4 + 3) * H_ + j];
        }
    }
    float4* dst = (float4*)(g_vproj + (long)v * H_);
    dst[0] = make_float4(ex2f(acc[0] * SCALE), ex2f(acc[1] * SCALE),
                         ex2f(acc[2] * SCALE), ex2f(acc[3] * SCALE));
    dst[1] = make_float4(ex2f(acc[4] * SCALE), ex2f(acc[5] * SCALE),
                         ex2f(acc[6] * SCALE), ex2f(acc[7] * SCALE));
}

// ---- mac stage: shfl + all 64 packed MACs (pure fma pipe) ----
__device__ __forceinline__ void mac_stage(
    const ull hp[4], ull ac[8], const ull* wx2, const ull* whh2) {
    ull vp[4];
#pragma unroll
    for (int p = 0; p < 4; p++) vp[p] = __shfl_up_sync(0xffffffffu, hp[p], 1);
#pragma unroll
    for (int j = 0; j < 8; j++) {
        ac[j] = mul2(hp[0], whh2[j * 4 + 0]);
        fma2(ac[j], hp[1], whh2[j * 4 + 1]);
        fma2(ac[j], hp[2], whh2[j * 4 + 2]);
        fma2(ac[j], hp[3], whh2[j * 4 + 3]);
#pragma unroll
        for (int p = 0; p < 4; p++) fma2(ac[j], vp[p], wx2[j * 4 + p]);
    }
}

// ---- act stage: r = 1/(2^y * C + 1) per unit (MUFU-heavy), guarded commit ----
__device__ __forceinline__ void act_stage(
    ull hp[4], const ull ac[8], const float* cptr, bool valid) {
    float4 c0 = ((const float4*)cptr)[0];
    float4 c1 = ((const float4*)cptr)[1];
    const float C[8] = {c0.x, c0.y, c0.z, c0.w, c1.x, c1.y, c1.z, c1.w};
    float n[8];
#pragma unroll
    for (int j = 0; j < 8; j++) {
        float2 u = upk(ac[j]);
        float e = ex2f(u.x + u.y);
        n[j] = rcpf(fmaf(e, C[j], 1.0f));
    }
    if (valid) {
#pragma unroll
        for (int p = 0; p < 4; p++) hp[p] = pk(n[2 * p], n[2 * p + 1]);
    }
}

// -------- Kernel 2: dual-element, stage-skewed (pipe-overlapped) wavefront ----
__global__ void __launch_bounds__(128, 1) rnn_sk_kernel(
    const int*   __restrict__ x,           // [B, T]
    const float* __restrict__ h0,          // [L, B, H]
    const float* __restrict__ W_xh_rest,   // [L-1, H, H]
    const float* __restrict__ W_hh,        // [L, H, H]
    const float* __restrict__ b_h,         // [L, H]
    const float* __restrict__ W_hy,        // [H, 1]
    const float* __restrict__ b_y,         // [1]
    float* __restrict__ out, int out_size) {

    extern __shared__ float smem[];
    float* sbias = smem;                   // [32][8] static exp-biases C (1 KB)
    float* sx    = smem + 32 * H_;         // [8 elems][T][8] C0 rows (128 KB)

    const int lane = threadIdx.x & 31;
    const int warp = threadIdx.x >> 5;     // 0..3, two elems per warp
    const int eA   = warp * 2;
    const int bA   = blockIdx.x * 8 + eA;
    const int bB   = bA + 1;
    const bool act   = (lane < L_);
    const bool hasWx = (lane >= 1) && act;
    const bool lane0 = (lane == 0);

    // ---- stage exp'd x-projection rows for this block's 8 elements ----
    {
        const ulonglong2* vp = (const ulonglong2*)g_vproj;
        ulonglong2* dst = (ulonglong2*)sx;
        for (int q = threadIdx.x; q < 8 * T_; q += 128) {
            int e = q >> 9;
            int t = q & (T_ - 1);
            int id = x[(long)(blockIdx.x * 8 + e) * T_ + t];
            dst[q * 2 + 0] = vp[(long)id * 2 + 0];
            dst[q * 2 + 1] = vp[(long)id * 2 + 1];
        }
    }

    // ---- weights, r-state transformed: W' = -2*SCALE*W; C = 2^(folded bias) ----
    ull wx2[32], whh2[32];
    float bsum[8];
#pragma unroll
    for (int j = 0; j < 8; j++) {
        float bs = 0.0f;   // SCALE * (b_j + sum_k Wx[k,j] + sum_k Whh[k,j])
#pragma unroll
        for (int p = 0; p < 4; p++) {
            float a = 0.f, c = 0.f;
            if (hasWx) {
                float w0 = W_xh_rest[((lane - 1) * H_ + 2 * p) * H_ + j];
                float w1 = W_xh_rest[((lane - 1) * H_ + 2 * p + 1) * H_ + j];
                a = -2.0f * SCALE * w0;
                c = -2.0f * SCALE * w1;
                bs += SCALE * (w0 + w1);
            }
            wx2[j * 4 + p] = pk(a, c);
            float d = 0.f, f = 0.f;
            if (act) {
                float w0 = W_hh[(lane * H_ + 2 * p) * H_ + j];
                float w1 = W_hh[(lane * H_ + 2 * p + 1) * H_ + j];
                d = -2.0f * SCALE * w0;
                f = -2.0f * SCALE * w1;
                bs += SCALE * (w0 + w1);
            }
            whh2[j * 4 + p] = pk(d, f);
        }
        if (hasWx) bs += SCALE * b_h[lane * H_ + j];
        bsum[j] = bs;
    }
    if (warp == 0) {
#pragma unroll
        for (int j = 0; j < 8; j++) sbias[lane * H_ + j] = ex2f(bsum[j]);
    }

    // ---- hidden state as r-form: r = (1 - h)/2 ----
    ull hpA[4], hpB[4];
#pragma unroll
    for (int p = 0; p < 4; p++) {
        float a0 = act ? h0[(lane * B_ + bA) * H_ + 2 * p]     : 0.f;
        float a1 = act ? h0[(lane * B_ + bA) * H_ + 2 * p + 1] : 0.f;
        hpA[p] = pk(0.5f * (1.0f - a0), 0.5f * (1.0f - a1));
        float c0 = act ? h0[(lane * B_ + bB) * H_ + 2 * p]     : 0.f;
        float c1 = act ? h0[(lane * B_ + bB) * H_ + 2 * p + 1] : 0.f;
        hpB[p] = pk(0.5f * (1.0f - c0), 0.5f * (1.0f - c1));
    }

    __syncthreads();

    // per-lane C pointers: lane0 walks its C0 stream, others static exp-bias
    const float* cptrA = lane0 ? (sx + (long)(eA + 0) * T_ * H_) : (sbias + lane * H_);
    const float* cptrB = lane0 ? (sx + (long)(eA + 1) * T_ * H_) : (sbias + lane * H_);
    const int binc = lane0 ? H_ : 0;

    ull acA[8], acB[8];
    // prologue: A's MACs for tick 0
    mac_stage(hpA, acA, wx2, whh2);

    // steady pipelined loop: [macB(s) | actA(s)] [macA(s+1) | actB(s)]
#pragma unroll 1
    for (int s = 0; s < TICKS; s++) {
        const bool valid = ((unsigned)(s - lane) < (unsigned)T_);
        mac_stage(hpB, acB, wx2, whh2);           // fma pipe (independent of actA)
        act_stage(hpA, acA, cptrA, valid);        // MUFU for A, commit hpA(s)
        mac_stage(hpA, acA, wx2, whh2);           // MACs for A(s+1) — overlaps actB
        act_stage(hpB, acB, cptrB, valid);        // MUFU for B, commit hpB(s)
        if (s < T_ - 1) { cptrA += binc; cptrB += binc; }
    }
    // (the trailing mac_stage(hpA) result in acA is unused — harmless)

    // ---- outputs: convert h = 1 - 2r ----
    if (act && out_size >= B_ + L_ * B_ * H_) {
#pragma unroll
        for (int p = 0; p < 4; p++) {
            float2 uA = upk(hpA[p]);
            out[B_ + (lane * B_ + bA) * H_ + 2 * p]     = fmaf(uA.x, -2.0f, 1.0f);
            out[B_ + (lane * B_ + bA) * H_ + 2 * p + 1] = fmaf(uA.y, -2.0f, 1.0f);
            float2 uB = upk(hpB[p]);
            out[B_ + (lane * B_ + bB) * H_ + 2 * p]     = fmaf(uB.x, -2.0f, 1.0f);
            out[B_ + (lane * B_ + bB) * H_ + 2 * p + 1] = fmaf(uB.y, -2.0f, 1.0f);
        }
    }
    if (lane == L_ - 1) {
        float sA = b_y[0], sB = b_y[0];
#pragma unroll
        for (int p = 0; p < 4; p++) {
            float2 uA = upk(hpA[p]);
            float2 uB = upk(hpB[p]);
            float w0 = W_hy[2 * p], w1 = W_hy[2 * p + 1];
            sA += fmaf(uA.x, -2.0f, 1.0f) * w0 + fmaf(uA.y, -2.0f, 1.0f) * w1;
            sB += fmaf(uB.x, -2.0f, 1.0f) * w0 + fmaf(uB.y, -2.0f, 1.0f) * w1;
        }
        if (bA < out_size) out[bA] = sA;
        if (bB < out_size) out[bB] = sB;
    }
}

extern "C" void kernel_launch(void* const* d_in, const int* in_sizes, int n_in,
                              void* d_out, int out_size) {
    const int*   x          = (const int*)d_in[0];
    const float* h0         = (const float*)d_in[1];
    const float* emb        = (const float*)d_in[2];
    const float* W_xh0      = (const float*)d_in[3];
    const float* W_xh_rest  = (const float*)d_in[4];
    const float* W_hh       = (const float*)d_in[5];
    const float* b_h        = (const float*)d_in[6];
    const float* W_hy       = (const float*)d_in[7];
    const float* b_y        = (const float*)d_in[8];

    vproj_kernel<<<(VOCAB_ + 255) / 256, 256>>>(emb, W_xh0, b_h, W_hh);

    const int smem_bytes = (32 * H_ + 8 * T_ * H_) * 4;   // 1 KB + 128 KB
    cudaFuncSetAttribute(rnn_sk_kernel,
                         cudaFuncAttributeMaxDynamicSharedMemorySize, smem_bytes);
    rnn_sk_kernel<<<B_ / 8, 128, smem_bytes>>>(x, h0, W_xh_rest, W_hh, b_h,
                                               W_hy, b_y, (float*)d_out, out_size);
}

// round 14
// speedup vs baseline: 1.0062x; 1.0010x over previous
#include <cuda_runtime.h>

#define VOCAB_ 32000
#define B_ 1000
#define T_ 512
#define L_ 25
#define E_ 64
#define H_ 8
#define TICKS (T_ + L_ - 1)        // 536
#define SCALE 2.8853900817779268f  // 2*log2(e), folded into weights

// vproj[v][j] = 2^( SCALE*(emb[v]@W_xh0[:,j] + b_h[0][j] + sum_k W_hh[0][k][j]) )
__device__ float g_vproj[(size_t)VOCAB_ * H_];

typedef unsigned long long ull;

__device__ __forceinline__ void fma2(ull& d, ull a, ull b) {
    asm("fma.rn.f32x2 %0, %1, %2, %0;" : "+l"(d) : "l"(a), "l"(b));
}
__device__ __forceinline__ ull mul2(ull a, ull b) {           // d = a*b (fresh dst)
    ull d; asm("mul.rn.f32x2 %0, %1, %2;" : "=l"(d) : "l"(a), "l"(b));
    return d;
}
__device__ __forceinline__ ull pk(float lo, float hi) {
    ull r; asm("mov.b64 %0, {%1, %2};" : "=l"(r) : "f"(lo), "f"(hi)); return r;
}
__device__ __forceinline__ float2 upk(ull p) {
    float2 r; asm("mov.b64 {%0, %1}, %2;" : "=f"(r.x), "=f"(r.y) : "l"(p)); return r;
}
__device__ __forceinline__ float ex2f(float y) {
    float e; asm("ex2.approx.f32 %0, %1;" : "=f"(e) : "f"(y)); return e;
}
__device__ __forceinline__ float rcpf(float d) {
    float r; asm("rcp.approx.f32 %0, %1;" : "=f"(r) : "f"(d)); return r;
}

// -------- Kernel 1: vproj = 2^(scaled xproj + layer-0 bias + Whh fold) --------
__global__ void vproj_kernel(const float* __restrict__ emb,
                             const float* __restrict__ W_xh0,
                             const float* __restrict__ b_h,
                             const float* __restrict__ W_hh) {
    __shared__ float sW[E_ * H_];
    __shared__ float sb[H_];    // b_h[0][j] + sum_k W_hh[0][k][j]
    for (int i = threadIdx.x; i < E_ * H_; i += blockDim.x) sW[i] = W_xh0[i];
    if (threadIdx.x < H_) {
        int j = threadIdx.x;
        float c = b_h[j];
#pragma unroll
        for (int k = 0; k < H_; k++) c += W_hh[k * H_ + j];   // layer 0 rows
        sb[j] = c;
    }
    __syncthreads();

    int v = blockIdx.x * blockDim.x + threadIdx.x;
    if (v >= VOCAB_) return;

    const float4* e4 = (const float4*)(emb + (long)v * E_);
    float acc[H_];
#pragma unroll
    for (int j = 0; j < H_; j++) acc[j] = sb[j];
#pragma unroll
    for (int k4 = 0; k4 < E_ / 4; k4++) {
        float4 ev = e4[k4];
#pragma unroll
        for (int j = 0; j < H_; j++) {
            acc[j] += ev.x * sW[(k4 * 4 + 0) * H_ + j];
            acc[j] += ev.y * sW[(k4 * 4 + 1) * H_ + j];
            acc[j] += ev.z * sW[(k4 * 4 + 2) * H_ + j];
            acc[j] += ev.w * sW[(k4 * 4 + 3) * H_ + j];
        }
    }
    float4* dst = (float4*)(g_vproj + (long)v * H_);
    dst[0] = make_float4(ex2f(acc[0] * SCALE), ex2f(acc[1] * SCALE),
                         ex2f(acc[2] * SCALE), ex2f(acc[3] * SCALE));
    dst[1] = make_float4(ex2f(acc[4] * SCALE), ex2f(acc[5] * SCALE),
                         ex2f(acc[6] * SCALE), ex2f(acc[7] * SCALE));
}

// ---- mac stage: shfl + all 64 packed MACs (pure fma pipe) ----
__device__ __forceinline__ void mac_stage(
    const ull hp[4], ull ac[8], const ull* wx2, const ull* whh2) {
    ull vp[4];
#pragma unroll
    for (int p = 0; p < 4; p++) vp[p] = __shfl_up_sync(0xffffffffu, hp[p], 1);
#pragma unroll
    for (int j = 0; j < 8; j++) {
        ac[j] = mul2(hp[0], whh2[j * 4 + 0]);
        fma2(ac[j], hp[1], whh2[j * 4 + 1]);
        fma2(ac[j], hp[2], whh2[j * 4 + 2]);
        fma2(ac[j], hp[3], whh2[j * 4 + 3]);
#pragma unroll
        for (int p = 0; p < 4; p++) fma2(ac[j], vp[p], wx2[j * 4 + p]);
    }
}

// ---- act stage: r = 1/(2^y * C + 1) per unit (MUFU-heavy), guarded commit ----
__device__ __forceinline__ void act_stage(
    ull hp[4], const ull ac[8], const float* cptr, bool valid) {
    float4 c0 = ((const float4*)cptr)[0];
    float4 c1 = ((const float4*)cptr)[1];
    const float C[8] = {c0.x, c0.y, c0.z, c0.w, c1.x, c1.y, c1.z, c1.w};
    float n[8];
#pragma unroll
    for (int j = 0; j < 8; j++) {
        float2 u = upk(ac[j]);
        float e = ex2f(u.x + u.y);
        n[j] = rcpf(fmaf(e, C[j], 1.0f));
    }
    if (valid) {
#pragma unroll
        for (int p = 0; p < 4; p++) hp[p] = pk(n[2 * p], n[2 * p + 1]);
    }
}

// -------- Kernel 2: warp-per-element wavefront, warp-parity phase offset ----
// Even warps: [mac(s); act(s)]. Odd warps: mac prologue, then [act(s); mac(s+1)].
// The half-tick offset interlocks the fma and MUFU bursts of the 2 warps
// sharing each SMSP, letting the pipes run concurrently.
__global__ void __launch_bounds__(256, 1) rnn_ph_kernel(
    const int*   __restrict__ x,           // [B, T]
    const float* __restrict__ h0,          // [L, B, H]
    const float* __restrict__ W_xh_rest,   // [L-1, H, H]
    const float* __restrict__ W_hh,        // [L, H, H]
    const float* __restrict__ b_h,         // [L, H]
    const float* __restrict__ W_hy,        // [H, 1]
    const float* __restrict__ b_y,         // [1]
    float* __restrict__ out, int out_size) {

    extern __shared__ float smem[];
    float* sbias = smem;                   // [32][8] static exp-biases C (1 KB)
    float* sx    = smem + 32 * H_;         // [8 elems][T][8] C0 rows (128 KB)

    const int lane = threadIdx.x & 31;
    const int warp = threadIdx.x >> 5;     // 0..7, one elem per warp
    const int b    = blockIdx.x * 8 + warp;
    const bool act   = (lane < L_);
    const bool hasWx = (lane >= 1) && act;
    const bool lane0 = (lane == 0);

    // ---- stage exp'd x-projection rows for this block's 8 elements ----
    {
        const ulonglong2* vp = (const ulonglong2*)g_vproj;
        ulonglong2* dst = (ulonglong2*)sx;
        for (int q = threadIdx.x; q < 8 * T_; q += 256) {
            int e = q >> 9;
            int t = q & (T_ - 1);
            int id = x[(long)(blockIdx.x * 8 + e) * T_ + t];
            dst[q * 2 + 0] = vp[(long)id * 2 + 0];
            dst[q * 2 + 1] = vp[(long)id * 2 + 1];
        }
    }

    // ---- weights, r-state transformed: W' = -2*SCALE*W; C = 2^(folded bias) ----
    ull wx2[32], whh2[32];
    float bsum[8];
#pragma unroll
    for (int j = 0; j < 8; j++) {
        float bs = 0.0f;   // SCALE * (b_j + sum_k Wx[k,j] + sum_k Whh[k,j])
#pragma unroll
        for (int p = 0; p < 4; p++) {
            float a = 0.f, c = 0.f;
            if (hasWx) {
                float w0 = W_xh_rest[((lane - 1) * H_ + 2 * p) * H_ + j];
                float w1 = W_xh_rest[((lane - 1) * H_ + 2 * p + 1) * H_ + j];
                a = -2.0f * SCALE * w0;
                c = -2.0f * SCALE * w1;
                bs += SCALE * (w0 + w1);
            }
            wx2[j * 4 + p] = pk(a, c);
            float d = 0.f, f = 0.f;
            if (act) {
                float w0 = W_hh[(lane * H_ + 2 * p) * H_ + j];
                float w1 = W_hh[(lane * H_ + 2 * p + 1) * H_ + j];
                d = -2.0f * SCALE * w0;
                f = -2.0f * SCALE * w1;
                bs += SCALE * (w0 + w1);
            }
            whh2[j * 4 + p] = pk(d, f);
        }
        if (hasWx) bs += SCALE * b_h[lane * H_ + j];
        bsum[j] = bs;
    }
    if (warp == 0) {
#pragma unroll
        for (int j = 0; j < 8; j++) sbias[lane * H_ + j] = ex2f(bsum[j]);
    }

    // ---- hidden state as r-form: r = (1 - h)/2 ----
    ull hp[4];
#pragma unroll
    for (int p = 0; p < 4; p++) {
        float a0 = act ? h0[(lane * B_ + b) * H_ + 2 * p]     : 0.f;
        float a1 = act ? h0[(lane * B_ + b) * H_ + 2 * p + 1] : 0.f;
        hp[p] = pk(0.5f * (1.0f - a0), 0.5f * (1.0f - a1));
    }

    __syncthreads();

    // per-lane C pointer: lane0 walks its C0 stream, others static exp-bias
    const float* cptr = lane0 ? (sx + (long)warp * T_ * H_) : (sbias + lane * H_);
    const int binc = lane0 ? H_ : 0;

    ull ac[8];
    if ((warp & 1) == 0) {
        // even warp: [mac(s); act(s)]
#pragma unroll 1
        for (int s = 0; s < TICKS; s++) {
            mac_stage(hp, ac, wx2, whh2);
            act_stage(hp, ac, cptr, (unsigned)(s - lane) < (unsigned)T_);
            if (s < T_ - 1) cptr += binc;
        }
    } else {
        // odd warp: half-tick ahead — mac prologue, then [act(s); mac(s+1)]
        mac_stage(hp, ac, wx2, whh2);
#pragma unroll 1
        for (int s = 0; s < TICKS; s++) {
            act_stage(hp, ac, cptr, (unsigned)(s - lane) < (unsigned)T_);
            if (s < T_ - 1) cptr += binc;
            mac_stage(hp, ac, wx2, whh2);     // tick s+1 (last one unused)
        }
    }

    // ---- outputs: convert h = 1 - 2r ----
    if (act && out_size >= B_ + L_ * B_ * H_) {
#pragma unroll
        for (int p = 0; p < 4; p++) {
            float2 u = upk(hp[p]);
            out[B_ + (lane * B_ + b) * H_ + 2 * p]     = fmaf(u.x, -2.0f, 1.0f);
            out[B_ + (lane * B_ + b) * H_ + 2 * p + 1] = fmaf(u.y, -2.0f, 1.0f);
        }
    }
    if (lane == L_ - 1) {
        float sv = b_y[0];
#pragma unroll
        for (int p = 0; p < 4; p++) {
            float2 u = upk(hp[p]);
            sv += fmaf(u.x, -2.0f, 1.0f) * W_hy[2 * p]
                + fmaf(u.y, -2.0f, 1.0f) * W_hy[2 * p + 1];
        }
        if (b < out_size) out[b] = sv;
    }
}

extern "C" void kernel_launch(void* const* d_in, const int* in_sizes, int n_in,
                              void* d_out, int out_size) {
    const int*   x          = (const int*)d_in[0];
    const float* h0         = (const float*)d_in[1];
    const float* emb        = (const float*)d_in[2];
    const float* W_xh0      = (const float*)d_in[3];
    const float* W_xh_rest  = (const float*)d_in[4];
    const float* W_hh       = (const float*)d_in[5];
    const float* b_h        = (const float*)d_in[6];
    const float* W_hy       = (const float*)d_in[7];
    const float* b_y        = (const float*)d_in[8];

    vproj_kernel<<<(VOCAB_ + 255) / 256, 256>>>(emb, W_xh0, b_h, W_hh);

    const int smem_bytes = (32 * H_ + 8 * T_ * H_) * 4;   // 1 KB + 128 KB
    cudaFuncSetAttribute(rnn_ph_kernel,
                         cudaFuncAttributeMaxDynamicSharedMemorySize, smem_bytes);
    rnn_ph_kernel<<<B_ / 8, 256, smem_bytes>>>(x, h0, W_xh_rest, W_hh, b_h,
                                               W_hy, b_y, (float*)d_out, out_size);
}

// round 15
// speedup vs baseline: 1.0492x; 1.0427x over previous
#include <cuda_runtime.h>

#define VOCAB_ 32000
#define B_ 1000
#define T_ 512
#define L_ 25
#define E_ 64
#define H_ 8
#define TICKS (T_ + L_ - 1)        // 536
#define SCALE 2.8853900817779268f  // 2*log2(e), folded into weights

// vproj[v][j] = 2^( SCALE*(emb[v]@W_xh0[:,j] + b_h[0][j] + sum_k W_hh[0][k][j]) )
__device__ float g_vproj[(size_t)VOCAB_ * H_];

typedef unsigned long long ull;

__device__ __forceinline__ void fma2(ull& d, ull a, ull b) {
    asm("fma.rn.f32x2 %0, %1, %2, %0;" : "+l"(d) : "l"(a), "l"(b));
}
__device__ __forceinline__ ull mul2(ull a, ull b) {           // d = a*b (fresh dst)
    ull d; asm("mul.rn.f32x2 %0, %1, %2;" : "=l"(d) : "l"(a), "l"(b));
    return d;
}
__device__ __forceinline__ ull pk(float lo, float hi) {
    ull r; asm("mov.b64 %0, {%1, %2};" : "=l"(r) : "f"(lo), "f"(hi)); return r;
}
__device__ __forceinline__ float2 upk(ull p) {
    float2 r; asm("mov.b64 {%0, %1}, %2;" : "=f"(r.x), "=f"(r.y) : "l"(p)); return r;
}
__device__ __forceinline__ float ex2f(float y) {
    float e; asm("ex2.approx.f32 %0, %1;" : "=f"(e) : "f"(y)); return e;
}
__device__ __forceinline__ float rcpf(float d) {
    float r; asm("rcp.approx.f32 %0, %1;" : "=f"(r) : "f"(d)); return r;
}

// -------- Kernel 1: vproj = 2^(scaled xproj + layer-0 bias + Whh fold) --------
__global__ void vproj_kernel(const float* __restrict__ emb,
                             const float* __restrict__ W_xh0,
                             const float* __restrict__ b_h,
                             const float* __restrict__ W_hh) {
    __shared__ float sW[E_ * H_];
    __shared__ float sb[H_];    // b_h[0][j] + sum_k W_hh[0][k][j]
    for (int i = threadIdx.x; i < E_ * H_; i += blockDim.x) sW[i] = W_xh0[i];
    if (threadIdx.x < H_) {
        int j = threadIdx.x;
        float c = b_h[j];
#pragma unroll
        for (int k = 0; k < H_; k++) c += W_hh[k * H_ + j];   // layer 0 rows
        sb[j] = c;
    }
    __syncthreads();

    int v = blockIdx.x * blockDim.x + threadIdx.x;
    if (v >= VOCAB_) return;

    const float4* e4 = (const float4*)(emb + (long)v * E_);
    float acc[H_];
#pragma unroll
    for (int j = 0; j < H_; j++) acc[j] = sb[j];
#pragma unroll
    for (int k4 = 0; k4 < E_ / 4; k4++) {
        float4 ev = e4[k4];
#pragma unroll
        for (int j = 0; j < H_; j++) {
            acc[j] += ev.x * sW[(k4 * 4 + 0) * H_ + j];
            acc[j] += ev.y * sW[(k4 * 4 + 1) * H_ + j];
            acc[j] += ev.z * sW[(k4 * 4 + 2) * H_ + j];
            acc[j] += ev.w * sW[(k4 * 4 + 3) * H_ + j];
        }
    }
    float4* dst = (float4*)(g_vproj + (long)v * H_);
    dst[0] = make_float4(ex2f(acc[0] * SCALE), ex2f(acc[1] * SCALE),
                         ex2f(acc[2] * SCALE), ex2f(acc[3] * SCALE));
    dst[1] = make_float4(ex2f(acc[4] * SCALE), ex2f(acc[5] * SCALE),
                         ex2f(acc[6] * SCALE), ex2f(acc[7] * SCALE));
}

// ---- mac: shfl + 64 packed MACs (pure fma pipe) ----
__device__ __forceinline__ void mac_tick(
    const ull hp[4], ull ac[8], const ull wx2[32], const ull whh2[32]) {
    ull vp0 = __shfl_up_sync(0xffffffffu, hp[0], 1);
    ull vp1 = __shfl_up_sync(0xffffffffu, hp[1], 1);
    ull vp2 = __shfl_up_sync(0xffffffffu, hp[2], 1);
    ull vp3 = __shfl_up_sync(0xffffffffu, hp[3], 1);
#pragma unroll
    for (int j = 0; j < 8; j++) {
        ull a = mul2(hp[0], whh2[j * 4 + 0]);
        fma2(a, hp[1], whh2[j * 4 + 1]);
        fma2(a, hp[2], whh2[j * 4 + 2]);
        fma2(a, hp[3], whh2[j * 4 + 3]);
        fma2(a, vp0, wx2[j * 4 + 0]);
        fma2(a, vp1, wx2[j * 4 + 1]);
        fma2(a, vp2, wx2[j * 4 + 2]);
        fma2(a, vp3, wx2[j * 4 + 3]);
        ac[j] = a;
    }
}

// ---- act: r = 1/(2^y * C + 1), commit (guarded only in ramp phases) ----
template<bool GUARD>
__device__ __forceinline__ void act_tick(
    ull hp[4], const ull ac[8], const float* cptr, bool valid) {
    float4 c0 = ((const float4*)cptr)[0];
    float4 c1 = ((const float4*)cptr)[1];
    const float C[8] = {c0.x, c0.y, c0.z, c0.w, c1.x, c1.y, c1.z, c1.w};
    float n[8];
#pragma unroll
    for (int j = 0; j < 8; j++) {
        float2 u = upk(ac[j]);
        float e = ex2f(u.x + u.y);
        n[j] = rcpf(fmaf(e, C[j], 1.0f));
    }
    if (!GUARD || valid) {
#pragma unroll
        for (int p = 0; p < 4; p++) hp[p] = pk(n[2 * p], n[2 * p + 1]);
    }
}

// -------- Kernel 2: warp-per-element wavefront, 3-phase + warp anti-phase ----
__global__ void __launch_bounds__(256, 1) rnn_ap_kernel(
    const int*   __restrict__ x,           // [B, T]
    const float* __restrict__ h0,          // [L, B, H]
    const float* __restrict__ W_xh_rest,   // [L-1, H, H]
    const float* __restrict__ W_hh,        // [L, H, H]
    const float* __restrict__ b_h,         // [L, H]
    const float* __restrict__ W_hy,        // [H, 1]
    const float* __restrict__ b_y,         // [1]
    float* __restrict__ out, int out_size) {

    extern __shared__ float smem[];
    float* sbias = smem;                   // [32][8] static exp-biases C (1 KB)
    float* sx    = smem + 32 * H_;         // [8 elems][T][8] C0 rows (128 KB)

    const int lane = threadIdx.x & 31;
    const int warp = threadIdx.x >> 5;     // 0..7, one elem per warp
    const int b    = blockIdx.x * 8 + warp;
    const bool act   = (lane < L_);
    const bool hasWx = (lane >= 1) && act;
    const bool lane0 = (lane == 0);

    // ---- stage exp'd x-projection rows for this block's 8 elements ----
    {
        const ulonglong2* vp = (const ulonglong2*)g_vproj;
        ulonglong2* dst = (ulonglong2*)sx;
        for (int q = threadIdx.x; q < 8 * T_; q += 256) {
            int e = q >> 9;
            int t = q & (T_ - 1);
            int id = x[(long)(blockIdx.x * 8 + e) * T_ + t];
            dst[q * 2 + 0] = vp[(long)id * 2 + 0];
            dst[q * 2 + 1] = vp[(long)id * 2 + 1];
        }
    }

    // ---- weights, r-state transformed: W' = -2*SCALE*W; C = 2^(folded bias) ----
    ull wx2[32], whh2[32];
    float bsum[8];
#pragma unroll
    for (int j = 0; j < 8; j++) {
        float bs = 0.0f;   // SCALE * (b_j + sum_k Wx[k,j] + sum_k Whh[k,j])
#pragma unroll
        for (int p = 0; p < 4; p++) {
            float a = 0.f, c = 0.f;
            if (hasWx) {
                float w0 = W_xh_rest[((lane - 1) * H_ + 2 * p) * H_ + j];
                float w1 = W_xh_rest[((lane - 1) * H_ + 2 * p + 1) * H_ + j];
                a = -2.0f * SCALE * w0;
                c = -2.0f * SCALE * w1;
                bs += SCALE * (w0 + w1);
            }
            wx2[j * 4 + p] = pk(a, c);
            float d = 0.f, f = 0.f;
            if (act) {
                float w0 = W_hh[(lane * H_ + 2 * p) * H_ + j];
                float w1 = W_hh[(lane * H_ + 2 * p + 1) * H_ + j];
                d = -2.0f * SCALE * w0;
                f = -2.0f * SCALE * w1;
                bs += SCALE * (w0 + w1);
            }
            whh2[j * 4 + p] = pk(d, f);
        }
        if (hasWx) bs += SCALE * b_h[lane * H_ + j];
        bsum[j] = bs;
    }
    if (warp == 0) {
#pragma unroll
        for (int j = 0; j < 8; j++) sbias[lane * H_ + j] = ex2f(bsum[j]);
    }

    // ---- hidden state as r-form: r = (1 - h)/2 ----
    ull hp[4];
#pragma unroll
    for (int p = 0; p < 4; p++) {
        float a0 = act ? h0[(lane * B_ + b) * H_ + 2 * p]     : 0.f;
        float a1 = act ? h0[(lane * B_ + b) * H_ + 2 * p + 1] : 0.f;
        hp[p] = pk(0.5f * (1.0f - a0), 0.5f * (1.0f - a1));
    }

    __syncthreads();

    // per-lane C pointer: lane0 walks its C0 stream, others static exp-bias
    const float* cptr = lane0 ? (sx + (long)warp * T_ * H_) : (sbias + lane * H_);
    const int binc = lane0 ? H_ : 0;

    ull ac[8];
    if ((warp & 1) == 0) {
        // even warp: [mac(s); act(s)] per tick, 3-phase guards
#pragma unroll 1
        for (int s = 0; s < L_ - 1; s++) {              // ramp-up
            mac_tick(hp, ac, wx2, whh2);
            act_tick<true>(hp, ac, cptr, s >= lane);
            cptr += binc;
        }
#pragma unroll 2
        for (int s = L_ - 1; s < T_ - 1; s++) {         // steady (no guards)
            mac_tick(hp, ac, wx2, whh2);
            act_tick<false>(hp, ac, cptr, true);
            cptr += binc;
        }
        mac_tick(hp, ac, wx2, whh2);                    // s = T-1
        act_tick<false>(hp, ac, cptr, true);
#pragma unroll 1
        for (int s = T_; s < TICKS; s++) {              // ramp-down
            mac_tick(hp, ac, wx2, whh2);
            act_tick<true>(hp, ac, cptr, lane >= s - (T_ - 1));
        }
    } else {
        // odd warp: half-tick ahead — mac prologue, then [act(s); mac(s+1)]
        mac_tick(hp, ac, wx2, whh2);                    // for s = 0
#pragma unroll 1
        for (int s = 0; s < L_ - 1; s++) {              // ramp-up
            act_tick<true>(hp, ac, cptr, s >= lane);
            cptr += binc;
            mac_tick(hp, ac, wx2, whh2);
        }
#pragma unroll 2
        for (int s = L_ - 1; s < T_ - 1; s++) {         // steady (no guards)
            act_tick<false>(hp, ac, cptr, true);
            cptr += binc;
            mac_tick(hp, ac, wx2, whh2);
        }
        act_tick<false>(hp, ac, cptr, true);            // s = T-1
        mac_tick(hp, ac, wx2, whh2);
#pragma unroll 1
        for (int s = T_; s < TICKS; s++) {              // ramp-down
            act_tick<true>(hp, ac, cptr, lane >= s - (T_ - 1));
            mac_tick(hp, ac, wx2, whh2);                // last one unused
        }
    }

    // ---- outputs: convert h = 1 - 2r ----
    if (act && out_size >= B_ + L_ * B_ * H_) {
#pragma unroll
        for (int p = 0; p < 4; p++) {
            float2 u = upk(hp[p]);
            out[B_ + (lane * B_ + b) * H_ + 2 * p]     = fmaf(u.x, -2.0f, 1.0f);
            out[B_ + (lane * B_ + b) * H_ + 2 * p + 1] = fmaf(u.y, -2.0f, 1.0f);
        }
    }
    if (lane == L_ - 1) {
        float sv = b_y[0];
#pragma unroll
        for (int p = 0; p < 4; p++) {
            float2 u = upk(hp[p]);
            sv += fmaf(u.x, -2.0f, 1.0f) * W_hy[2 * p]
                + fmaf(u.y, -2.0f, 1.0f) * W_hy[2 * p + 1];
        }
        if (b < out_size) out[b] = sv;
    }
}

extern "C" void kernel_launch(void* const* d_in, const int* in_sizes, int n_in,
                              void* d_out, int out_size) {
    const int*   x          = (const int*)d_in[0];
    const float* h0         = (const float*)d_in[1];
    const float* emb        = (const float*)d_in[2];
    const float* W_xh0      = (const float*)d_in[3];
    const float* W_xh_rest  = (const float*)d_in[4];
    const float* W_hh       = (const float*)d_in[5];
    const float* b_h        = (const float*)d_in[6];
    const float* W_hy       = (const float*)d_in[7];
    const float* b_y        = (const float*)d_in[8];

    vproj_kernel<<<(VOCAB_ + 255) / 256, 256>>>(emb, W_xh0, b_h, W_hh);

    const int smem_bytes = (32 * H_ + 8 * T_ * H_) * 4;   // 1 KB + 128 KB
    cudaFuncSetAttribute(rnn_ap_kernel,
                         cudaFuncAttributeMaxDynamicSharedMemorySize, smem_bytes);
    rnn_ap_kernel<<<B_ / 8, 256, smem_bytes>>>(x, h0, W_xh_rest, W_hh, b_h,
                                               W_hy, b_y, (float*)d_out, out_size);
}

// round 16
// speedup vs baseline: 1.0704x; 1.0202x over previous
#include <cuda_runtime.h>

#define VOCAB_ 32000
#define B_ 1000
#define T_ 512
#define L_ 25
#define E_ 64
#define H_ 8
#define TICKS (T_ + L_ - 1)        // 536
#define SCALE 2.8853900817779268f  // 2*log2(e), folded into weights

// vproj[v][j] = 2^( SCALE*(emb[v]@W_xh0[:,j] + b_h[0][j] + sum_k W_hh[0][k][j]) )
__device__ float g_vproj[(size_t)VOCAB_ * H_];

typedef unsigned long long ull;

__device__ __forceinline__ void fma2(ull& d, ull a, ull b) {
    asm("fma.rn.f32x2 %0, %1, %2, %0;" : "+l"(d) : "l"(a), "l"(b));
}
__device__ __forceinline__ ull mul2(ull a, ull b) {           // d = a*b (fresh dst)
    ull d; asm("mul.rn.f32x2 %0, %1, %2;" : "=l"(d) : "l"(a), "l"(b));
    return d;
}
__device__ __forceinline__ ull pk(float lo, float hi) {
    ull r; asm("mov.b64 %0, {%1, %2};" : "=l"(r) : "f"(lo), "f"(hi)); return r;
}
__device__ __forceinline__ float2 upk(ull p) {
    float2 r; asm("mov.b64 {%0, %1}, %2;" : "=f"(r.x), "=f"(r.y) : "l"(p)); return r;
}
__device__ __forceinline__ float ex2f(float y) {
    float e; asm("ex2.approx.f32 %0, %1;" : "=f"(e) : "f"(y)); return e;
}
__device__ __forceinline__ float rcpf(float d) {
    float r; asm("rcp.approx.f32 %0, %1;" : "=f"(r) : "f"(d)); return r;
}

// -------- Kernel 1: vproj = 2^(scaled xproj + layer-0 bias + Whh fold) --------
__global__ void vproj_kernel(const float* __restrict__ emb,
                             const float* __restrict__ W_xh0,
                             const float* __restrict__ b_h,
                             const float* __restrict__ W_hh) {
    __shared__ float sW[E_ * H_];
    __shared__ float sb[H_];    // b_h[0][j] + sum_k W_hh[0][k][j]
    for (int i = threadIdx.x; i < E_ * H_; i += blockDim.x) sW[i] = W_xh0[i];
    if (threadIdx.x < H_) {
        int j = threadIdx.x;
        float c = b_h[j];
#pragma unroll
        for (int k = 0; k < H_; k++) c += W_hh[k * H_ + j];   // layer 0 rows
        sb[j] = c;
    }
    __syncthreads();

    int v = blockIdx.x * blockDim.x + threadIdx.x;
    if (v >= VOCAB_) return;

    const float4* e4 = (const float4*)(emb + (long)v * E_);
    float acc[H_];
#pragma unroll
    for (int j = 0; j < H_; j++) acc[j] = sb[j];
#pragma unroll
    for (int k4 = 0; k4 < E_ / 4; k4++) {
        float4 ev = e4[k4];
#pragma unroll
        for (int j = 0; j < H_; j++) {
            acc[j] += ev.x * sW[(k4 * 4 + 0) * H_ + j];
            acc[j] += ev.y * sW[(k4 * 4 + 1) * H_ + j];
            acc[j] += ev.z * sW[(k4 * 4 + 2) * H_ + j];
            acc[j] += ev.w * sW[(k4 * 4 + 3) * H_ + j];
        }
    }
    float4* dst = (float4*)(g_vproj + (long)v * H_);
    dst[0] = make_float4(ex2f(acc[0] * SCALE), ex2f(acc[1] * SCALE),
                         ex2f(acc[2] * SCALE), ex2f(acc[3] * SCALE));
    dst[1] = make_float4(ex2f(acc[4] * SCALE), ex2f(acc[5] * SCALE),
                         ex2f(acc[6] * SCALE), ex2f(acc[7] * SCALE));
}

// ---- one wavefront tick (r-state, C-form activation). Per-lane C row from
// smem: lane0's row is its exp'd x-projection (ptr advances), lanes>=1 read
// their static exp'd folded bias. r = 1/(2^y * C + 1); tanh(x) = 1 - 2r.
template<bool GUARD>
__device__ __forceinline__ void tick(
    ull hp[4], const ull wx2[32], const ull whh2[32],
    const float* cptr, bool valid) {

    float4 c0 = ((const float4*)cptr)[0];
    float4 c1 = ((const float4*)cptr)[1];

    ull vp0 = __shfl_up_sync(0xffffffffu, hp[0], 1);
    ull vp1 = __shfl_up_sync(0xffffffffu, hp[1], 1);
    ull vp2 = __shfl_up_sync(0xffffffffu, hp[2], 1);
    ull vp3 = __shfl_up_sync(0xffffffffu, hp[3], 1);

    ull ac[8];
#pragma unroll
    for (int j = 0; j < 8; j++) {
        ull a = mul2(hp[0], whh2[j * 4 + 0]);
        fma2(a, hp[1], whh2[j * 4 + 1]);
        fma2(a, hp[2], whh2[j * 4 + 2]);
        fma2(a, hp[3], whh2[j * 4 + 3]);
        fma2(a, vp0, wx2[j * 4 + 0]);
        fma2(a, vp1, wx2[j * 4 + 1]);
        fma2(a, vp2, wx2[j * 4 + 2]);
        fma2(a, vp3, wx2[j * 4 + 3]);
        ac[j] = a;
    }
    const float C[8] = {c0.x, c0.y, c0.z, c0.w, c1.x, c1.y, c1.z, c1.w};
    float n[8];
#pragma unroll
    for (int j = 0; j < 8; j++) {
        float2 u = upk(ac[j]);
        float e = ex2f(u.x + u.y);
        n[j] = rcpf(fmaf(e, C[j], 1.0f));
    }
    if (GUARD) {
        if (valid) {
#pragma unroll
            for (int p = 0; p < 4; p++) hp[p] = pk(n[2 * p], n[2 * p + 1]);
        }
    } else {
#pragma unroll
        for (int p = 0; p < 4; p++) hp[p] = pk(n[2 * p], n[2 * p + 1]);
    }
}

// -------- Kernel 2: warp-per-element wavefront, smem C-stream inject --------
__global__ void __launch_bounds__(256, 1) rnn_cf_kernel(
    const int*   __restrict__ x,           // [B, T]
    const float* __restrict__ h0,          // [L, B, H]
    const float* __restrict__ W_xh_rest,   // [L-1, H, H]
    const float* __restrict__ W_hh,        // [L, H, H]
    const float* __restrict__ b_h,         // [L, H]
    const float* __restrict__ W_hy,        // [H, 1]
    const float* __restrict__ b_y,         // [1]
    float* __restrict__ out, int out_size) {

    extern __shared__ float smem[];
    float* sbias = smem;                   // [32][8] static exp-biases C (1 KB)
    float* sx    = smem + 32 * H_;         // [8 elems][T][8] C0 rows (128 KB)

    const int lane = threadIdx.x & 31;
    const int warp = threadIdx.x >> 5;     // 0..7, one elem per warp
    const int b    = blockIdx.x * 8 + warp;
    const bool act   = (lane < L_);
    const bool hasWx = (lane >= 1) && act;
    const bool lane0 = (lane == 0);

    // ---- stage exp'd x-projection rows for this block's 8 elements ----
    {
        const ulonglong2* vp = (const ulonglong2*)g_vproj;
        ulonglong2* dst = (ulonglong2*)sx;
        for (int q = threadIdx.x; q < 8 * T_; q += 256) {
            int e = q >> 9;
            int t = q & (T_ - 1);
            int id = x[(long)(blockIdx.x * 8 + e) * T_ + t];
            dst[q * 2 + 0] = vp[(long)id * 2 + 0];
            dst[q * 2 + 1] = vp[(long)id * 2 + 1];
        }
    }

    // ---- weights, r-state transformed: W' = -2*SCALE*W; C = 2^(folded bias) ----
    ull wx2[32], whh2[32];
    float bsum[8];
#pragma unroll
    for (int j = 0; j < 8; j++) {
        float bs = 0.0f;   // SCALE * (b_j + sum_k Wx[k,j] + sum_k Whh[k,j])
#pragma unroll
        for (int p = 0; p < 4; p++) {
            float a = 0.f, c = 0.f;
            if (hasWx) {
                float w0 = W_xh_rest[((lane - 1) * H_ + 2 * p) * H_ + j];
                float w1 = W_xh_rest[((lane - 1) * H_ + 2 * p + 1) * H_ + j];
                a = -2.0f * SCALE * w0;
                c = -2.0f * SCALE * w1;
                bs += SCALE * (w0 + w1);
            }
            wx2[j * 4 + p] = pk(a, c);
            float d = 0.f, f = 0.f;
            if (act) {
                float w0 = W_hh[(lane * H_ + 2 * p) * H_ + j];
                float w1 = W_hh[(lane * H_ + 2 * p + 1) * H_ + j];
                d = -2.0f * SCALE * w0;
                f = -2.0f * SCALE * w1;
                bs += SCALE * (w0 + w1);
            }
            whh2[j * 4 + p] = pk(d, f);
        }
        if (hasWx) bs += SCALE * b_h[lane * H_ + j];
        bsum[j] = bs;
    }
    if (warp == 0) {
#pragma unroll
        for (int j = 0; j < 8; j++) sbias[lane * H_ + j] = ex2f(bsum[j]);
    }

    // ---- hidden state as r-form: r = (1 - h)/2 ----
    ull hp[4];
#pragma unroll
    for (int p = 0; p < 4; p++) {
        float a0 = act ? h0[(lane * B_ + b) * H_ + 2 * p]     : 0.f;
        float a1 = act ? h0[(lane * B_ + b) * H_ + 2 * p + 1] : 0.f;
        hp[p] = pk(0.5f * (1.0f - a0), 0.5f * (1.0f - a1));
    }

    __syncthreads();

    // per-lane C pointer: lane0 walks its C0 stream, others static exp-bias
    const float* cptr = lane0 ? (sx + (long)warp * T_ * H_) : (sbias + lane * H_);
    const int binc = lane0 ? H_ : 0;

    int s = 0;
    // ---- ramp-up: guarded commits ----
#pragma unroll 1
    for (; s < L_ - 1; s++) {
        tick<true>(hp, wx2, whh2, cptr, s >= lane);
        cptr += binc;
    }
    // ---- steady: unconditional commits ----
#pragma unroll 4
    for (; s < T_; s++) {
        tick<false>(hp, wx2, whh2, cptr, true);
        cptr += binc;
    }
    cptr -= binc;   // clamp: lane0 re-reads C0(T-1) during ramp-down (unused)
    // ---- ramp-down: guarded (freeze finished lanes) ----
#pragma unroll 1
    for (; s < TICKS; s++) {
        tick<true>(hp, wx2, whh2, cptr, lane >= s - (T_ - 1));
    }

    // ---- outputs: convert h = 1 - 2r ----
    if (act && out_size >= B_ + L_ * B_ * H_) {
#pragma unroll
        for (int p = 0; p < 4; p++) {
            float2 u = upk(hp[p]);
            out[B_ + (lane * B_ + b) * H_ + 2 * p]     = fmaf(u.x, -2.0f, 1.0f);
            out[B_ + (lane * B_ + b) * H_ + 2 * p + 1] = fmaf(u.y, -2.0f, 1.0f);
        }
    }
    if (lane == L_ - 1) {
        float sv = b_y[0];
#pragma unroll
        for (int p = 0; p < 4; p++) {
            float2 u = upk(hp[p]);
            sv += fmaf(u.x, -2.0f, 1.0f) * W_hy[2 * p]
                + fmaf(u.y, -2.0f, 1.0f) * W_hy[2 * p + 1];
        }
        if (b < out_size) out[b] = sv;
    }
}

extern "C" void kernel_launch(void* const* d_in, const int* in_sizes, int n_in,
                              void* d_out, int out_size) {
    const int*   x          = (const int*)d_in[0];
    const float* h0         = (const float*)d_in[1];
    const float* emb        = (const float*)d_in[2];
    const float* W_xh0      = (const float*)d_in[3];
    const float* W_xh_rest  = (const float*)d_in[4];
    const float* W_hh       = (const float*)d_in[5];
    const float* b_h        = (const float*)d_in[6];
    const float* W_hy       = (const float*)d_in[7];
    const float* b_y        = (const float*)d_in[8];

    vproj_kernel<<<(VOCAB_ + 255) / 256, 256>>>(emb, W_xh0, b_h, W_hh);

    const int smem_bytes = (32 * H_ + 8 * T_ * H_) * 4;   // 1 KB + 128 KB
    cudaFuncSetAttribute(rnn_cf_kernel,
                         cudaFuncAttributeMaxDynamicSharedMemorySize, smem_bytes);
    rnn_cf_kernel<<<B_ / 8, 256, smem_bytes>>>(x, h0, W_xh_rest, W_hh, b_h,
                                               W_hy, b_y, (float*)d_out, out_size);
}